// round 2
// baseline (speedup 1.0000x reference)
#include <cuda_runtime.h>
#include <math.h>

#define T_MAX   10000
#define BATCH   4096
#define CHUNK   64
#define NCHUNKS ((T_MAX + CHUNK - 1) / CHUNK)
#define PRE_NT  1024
#define PRE_NP  ((T_MAX + PRE_NT - 1) / PRE_NT)   // 10

// fp32-cast constants, matching reference's float(np.log(...))
#define LOG_GAMMA_F  0.019802627296179713f   // log(1.02)
#define ALPHA_F     (-1.005033585350145e-05f) // log(0.99)/1000
#define INIT_LOGW_F (-1.3943265327958258f)   // log(0.248)
#define INIT_LOGP_F (-6.907755278982137f)    // log(0.001)
#define EPS_F        1e-12f

// ---------------- device globals (scratch; no allocation allowed) -------------
__device__ float g_m[T_MAX];          // threshold m_t = p/(1-p) - eps
__device__ float g_logwB[T_MAX];      // logw before step t
__device__ float g_logwA[T_MAX];      // logw after step t
__device__ float g_prefW[T_MAX + 1];  // exclusive prefix of w_t
__device__ int   g_Tcut;              // first t after which no trigger possible
__device__ int   g_td[BATCH];         // first trigger time per batch elem (T_MAX = survivor)

// ---------------- compensated fp32 (hi,lo) arithmetic -------------------------
struct DS { float hi, lo; };

__device__ __forceinline__ DS ds_make(float h) { DS r; r.hi = h; r.lo = 0.f; return r; }

__device__ __forceinline__ DS ds_add(DS a, float b) {
    float s  = a.hi + b;
    float bb = s - a.hi;
    float err = (a.hi - (s - bb)) + (b - bb);
    err += a.lo;
    DS r; r.hi = s + err; r.lo = err - (r.hi - s);
    return r;
}

__device__ __forceinline__ DS ds_add2(DS a, DS b) {
    float s  = a.hi + b.hi;
    float bb = s - a.hi;
    float err = (a.hi - (s - bb)) + (b.hi - bb);
    err += a.lo + b.lo;
    DS r; r.hi = s + err; r.lo = err - (r.hi - s);
    return r;
}

// Block-wide exclusive scan of one DS value per thread (Hillis-Steele).
__device__ __forceinline__ DS block_excl_scan(DS v, DS* sh, int tid) {
    sh[tid] = v;
    __syncthreads();
    for (int ofs = 1; ofs < PRE_NT; ofs <<= 1) {
        DS t = ds_make(0.f);
        if (tid >= ofs) t = sh[tid - ofs];
        __syncthreads();
        if (tid >= ofs) sh[tid] = ds_add2(sh[tid], t);
        __syncthreads();
    }
    DS excl = (tid > 0) ? sh[tid - 1] : ds_make(0.f);
    __syncthreads();
    return excl;
}

// ---------------- kernel 1: per-timestep precompute ---------------------------
__global__ __launch_bounds__(PRE_NT)
void precompute_kernel(const float* __restrict__ acts) {
    __shared__ DS sh[PRE_NT];
    __shared__ int shMax;
    const int tid  = threadIdx.x;
    const int base = tid * PRE_NP;
    if (tid == 0) shMax = -1;

    // init per-batch first-trigger array
    for (int b = tid; b < BATCH; b += PRE_NT) g_td[b] = T_MAX;
    __syncthreads();

    // ---- pass A: d_t = LOG_GAMMA + log1p(-exp(a_t)) ; scan -> logw ----
    DS s = ds_make(0.f);
    #pragma unroll
    for (int k = 0; k < PRE_NP; k++) {
        int t = base + k;
        if (t < T_MAX) {
            float f = expf(acts[t]);
            float d = LOG_GAMMA_F + log1pf(-f);
            s = ds_add(s, d);
        }
    }
    DS off = block_excl_scan(s, sh, tid);
    DS run = ds_add2(ds_make(INIT_LOGW_F), off);
    #pragma unroll
    for (int k = 0; k < PRE_NP; k++) {
        int t = base + k;
        if (t < T_MAX) {
            float f = expf(acts[t]);
            float d = LOG_GAMMA_F + log1pf(-f);
            g_logwB[t] = run.hi;
            run = ds_add(run, d);
            g_logwA[t] = run.hi;
        }
    }
    __syncthreads();

    // ---- pass B: e_t = ALPHA * f_t * exp(logwB_t) ; scan -> logp ; m_t ----
    DS s2 = ds_make(0.f);
    #pragma unroll
    for (int k = 0; k < PRE_NP; k++) {
        int t = base + k;
        if (t < T_MAX) {
            float f = expf(acts[t]);
            float e = ALPHA_F * f * expf(g_logwB[t]);
            s2 = ds_add(s2, e);
        }
    }
    DS off2 = block_excl_scan(s2, sh, tid);
    DS run2 = ds_add2(ds_make(INIT_LOGP_F), off2);
    int locMax = -1;
    #pragma unroll
    for (int k = 0; k < PRE_NP; k++) {
        int t = base + k;
        if (t < T_MAX) {
            float logp = run2.hi;
            float p    = expf(logp);
            float thr  = p / (1.0f - p);
            float m    = thr - EPS_F;
            g_m[t] = m;
            if (m > 0.f) locMax = t;
            float f = expf(acts[t]);
            float e = ALPHA_F * f * expf(g_logwB[t]);
            run2 = ds_add(run2, e);
        }
    }
    atomicMax(&shMax, locMax);
    __syncthreads();
    if (tid == 0) g_Tcut = shMax + 1;

    // ---- pass C: w_t = exp(logwA_t / 1000) ; exclusive scan -> prefW ----
    DS s3 = ds_make(0.f);
    #pragma unroll
    for (int k = 0; k < PRE_NP; k++) {
        int t = base + k;
        if (t < T_MAX) {
            float w = expf(g_logwA[t] * (1.0f / 1000.0f));
            s3 = ds_add(s3, w);
        }
    }
    DS off3 = block_excl_scan(s3, sh, tid);
    DS run3 = off3;
    #pragma unroll
    for (int k = 0; k < PRE_NP; k++) {
        int t = base + k;
        if (t < T_MAX) {
            float w = expf(g_logwA[t] * (1.0f / 1000.0f));
            g_prefW[t] = run3.hi;
            run3 = ds_add(run3, w);
            if (t + 1 == T_MAX) g_prefW[T_MAX] = run3.hi;
        }
    }
}

// ---------------- kernel 2: find first trigger per batch element --------------
__global__ __launch_bounds__(256)
void scan_kernel(const float* __restrict__ u1, const float* __restrict__ u2) {
    const int t0 = blockIdx.y * CHUNK;
    const int Tc = g_Tcut;
    if (t0 >= Tc) return;               // uniform exit: chunks past cutoff do nothing

    __shared__ float sm[CHUNK];
    const int tid = threadIdx.x;
    if (tid < CHUNK) {
        int tt = t0 + tid;
        sm[tid] = (tt < T_MAX) ? g_m[tt] : -1.0f;
    }
    __syncthreads();

    const int b = blockIdx.x * blockDim.x + tid;
    if (g_td[b] <= t0) return;          // already died in an earlier chunk (monotone-safe)

    const int n = min(CHUNK, Tc - t0);
    const float* p1 = u1 + (size_t)t0 * BATCH + b;
    const float* p2 = u2 + (size_t)t0 * BATCH + b;

    int i = 0;
    for (; i + 4 <= n; i += 4) {
        float a0 = p1[0], a1 = p1[BATCH], a2 = p1[2 * BATCH], a3 = p1[3 * BATCH];
        float c0 = p2[0], c1 = p2[BATCH], c2 = p2[2 * BATCH], c3 = p2[3 * BATCH];
        p1 += 4 * BATCH; p2 += 4 * BATCH;
        float l10 = __logf(a0 + EPS_F), l11 = __logf(a1 + EPS_F);
        float l12 = __logf(a2 + EPS_F), l13 = __logf(a3 + EPS_F);
        float l20 = __logf(c0 + EPS_F), l21 = __logf(c1 + EPS_F);
        float l22 = __logf(c2 + EPS_F), l23 = __logf(c3 + EPS_F);
        bool h0 = l20 > sm[i + 0] * l10;
        bool h1 = l21 > sm[i + 1] * l11;
        bool h2 = l22 > sm[i + 2] * l12;
        bool h3 = l23 > sm[i + 3] * l13;
        if (h0 | h1 | h2 | h3) {
            int t = t0 + (h0 ? i : (h1 ? i + 1 : (h2 ? i + 2 : i + 3)));
            atomicMin(&g_td[b], t);
            return;
        }
    }
    for (; i < n; ++i) {
        float l1 = __logf(p1[0] + EPS_F);
        float l2 = __logf(p2[0] + EPS_F);
        p1 += BATCH; p2 += BATCH;
        if (l2 > sm[i] * l1) {
            atomicMin(&g_td[b], t0 + i);
            return;
        }
    }
}

// ---------------- kernel 3: deterministic mean reduction ----------------------
__global__ __launch_bounds__(1024)
void finalize_kernel(float* __restrict__ out) {
    __shared__ double sh[1024];
    const int tid = threadIdx.x;
    double s = 0.0;
    for (int b = tid; b < BATCH; b += 1024)
        s += (double)g_prefW[g_td[b]];
    sh[tid] = s;
    __syncthreads();
    for (int ofs = 512; ofs > 0; ofs >>= 1) {
        if (tid < ofs) sh[tid] += sh[tid + ofs];
        __syncthreads();
    }
    if (tid == 0) out[0] = (float)(sh[0] * (1.0 / (double)BATCH));
}

// ---------------- launch -----------------------------------------------------
extern "C" void kernel_launch(void* const* d_in, const int* in_sizes, int n_in,
                              void* d_out, int out_size) {
    const float* acts = (const float*)d_in[0];
    const float* u1   = (const float*)d_in[1];
    const float* u2   = (const float*)d_in[2];
    float* out = (float*)d_out;

    precompute_kernel<<<1, PRE_NT>>>(acts);
    dim3 grid(BATCH / 256, NCHUNKS);
    scan_kernel<<<grid, 256>>>(u1, u2);
    finalize_kernel<<<1, 1024>>>(out);
}

// round 3
// speedup vs baseline: 1.0729x; 1.0729x over previous
#include <cuda_runtime.h>
#include <math.h>

#define T_MAX   10000
#define BATCH   4096
#define CHUNK   64
#define NCHUNKS ((T_MAX + CHUNK - 1) / CHUNK)
#define NB      40
#define NT      256

// fp32-cast constants, matching reference's float(np.log(...))
#define LOG_GAMMA_F  0.019802627296179713f    // log(1.02)
#define ALPHA_F     (-1.005033585350145e-05f) // log(0.99)/1000
#define INIT_LOGW_F (-1.3943265327958258f)    // log(0.248)
#define INIT_LOGP_F (-6.907755278982137f)     // log(0.001)
#define EPS_F        1e-12f
#define L1MIN_MAG    27.632f                  // |log(1e-12)| + margin (conservative filter)

// ---------------- device globals (scratch; no allocation allowed) -------------
__device__ float  g_f[NB * NT];        // f_t = exp(a_t)
__device__ float  g_d[NB * NT];        // d_t = log_gamma + log1p(-f)
__device__ float  g_e[NB * NT];        // e_t = alpha * f * exp(logwB)
__device__ float  g_w[NB * NT];        // w_t = exp(logwA/1000)
__device__ float  g_m[T_MAX];          // threshold m_t = p/(1-p) - eps
__device__ float  g_c[T_MAX];          // filter threshold exp(-27.632*m) (2.0 = never)
__device__ float  g_prefW[T_MAX + 1];  // exclusive prefix of w_t
__device__ float2 g_blkD[NB], g_blkE[NB], g_blkW[NB];   // per-block DS sums
__device__ float2 g_offD[NB], g_offE[NB], g_offW[NB];   // exclusive block offsets
__device__ int    g_TcutM1;            // last t with m>0 (Tcut-1)
__device__ int    g_td[BATCH];         // first trigger time per batch elem

// ---------------- compensated fp32 (hi,lo) arithmetic -------------------------
struct DS { float hi, lo; };

__device__ __forceinline__ DS ds_make(float h) { DS r; r.hi = h; r.lo = 0.f; return r; }
__device__ __forceinline__ DS ds_of(float2 v)  { DS r; r.hi = v.x; r.lo = v.y; return r; }
__device__ __forceinline__ float2 ds_pack(DS a){ return make_float2(a.hi, a.lo); }

__device__ __forceinline__ DS ds_add(DS a, float b) {
    float s  = a.hi + b;
    float bb = s - a.hi;
    float err = (a.hi - (s - bb)) + (b - bb);
    err += a.lo;
    DS r; r.hi = s + err; r.lo = err - (r.hi - s);
    return r;
}

__device__ __forceinline__ DS ds_add2(DS a, DS b) {
    float s  = a.hi + b.hi;
    float bb = s - a.hi;
    float err = (a.hi - (s - bb)) + (b.hi - bb);
    err += a.lo + b.lo;
    DS r; r.hi = s + err; r.lo = err - (r.hi - s);
    return r;
}

// Block-wide exclusive scan of one DS per thread (Hillis-Steele, NT threads).
// After return, sh[] is destroyed; *total = inclusive sum of whole block.
__device__ __forceinline__ DS block_scan_excl(DS v, DS* sh, int tid, DS* total) {
    sh[tid] = v;
    __syncthreads();
    #pragma unroll
    for (int ofs = 1; ofs < NT; ofs <<= 1) {
        DS t = (tid >= ofs) ? sh[tid - ofs] : ds_make(0.f);
        __syncthreads();
        if (tid >= ofs) sh[tid] = ds_add2(sh[tid], t);
        __syncthreads();
    }
    DS excl = (tid > 0) ? sh[tid - 1] : ds_make(0.f);
    if (total) *total = sh[NT - 1];
    __syncthreads();
    return excl;
}

// ---------------- P1: per-element f,d + block sums of d + init ---------------
__global__ __launch_bounds__(NT)
void p1_kernel(const float* __restrict__ acts) {
    __shared__ DS sh[NT];
    const int tid = threadIdx.x;
    const int t   = blockIdx.x * NT + tid;

    if (t < BATCH) g_td[t] = T_MAX;
    if (t == 0)    g_TcutM1 = -1;

    DS v = ds_make(0.f);
    float f = 0.f, d = 0.f;
    if (t < T_MAX) {
        f = expf(acts[t]);
        d = LOG_GAMMA_F + log1pf(-f);
        v = ds_make(d);
    }
    g_f[t] = f;
    g_d[t] = d;

    DS tot;
    (void)block_scan_excl(v, sh, tid, &tot);
    if (tid == 0) g_blkD[blockIdx.x] = ds_pack(tot);
}

// ---------------- P2: scan 40 block sums of d --------------------------------
__global__ void p2_kernel() {
    if (threadIdx.x == 0) {
        DS s = ds_make(0.f);
        for (int b = 0; b < NB; b++) {
            g_offD[b] = ds_pack(s);
            s = ds_add2(s, ds_of(g_blkD[b]));
        }
    }
}

// ---------------- P3: logw per element -> e,w + block sums -------------------
__global__ __launch_bounds__(NT)
void p3_kernel() {
    __shared__ DS sh[NT];
    const int tid = threadIdx.x;
    const int t   = blockIdx.x * NT + tid;

    float d = g_d[t];
    DS v = (t < T_MAX) ? ds_make(d) : ds_make(0.f);
    DS excl = block_scan_excl(v, sh, tid, nullptr);

    DS logwB = ds_add2(ds_add2(ds_make(INIT_LOGW_F), ds_of(g_offD[blockIdx.x])), excl);
    DS logwA = ds_add(logwB, d);

    float e = 0.f, w = 0.f;
    if (t < T_MAX) {
        float f = g_f[t];
        e = ALPHA_F * f * expf(logwB.hi);
        w = expf(logwA.hi * (1.0f / 1000.0f));
    }
    g_e[t] = e;
    g_w[t] = w;

    DS totE, totW;
    (void)block_scan_excl(ds_make(e), sh, tid, &totE);
    (void)block_scan_excl(ds_make(w), sh, tid, &totW);
    if (tid == 0) {
        g_blkE[blockIdx.x] = ds_pack(totE);
        g_blkW[blockIdx.x] = ds_pack(totW);
    }
}

// ---------------- P4: scan 40 block sums of e and w --------------------------
__global__ void p4_kernel() {
    if (threadIdx.x == 0) {
        DS s = ds_make(0.f);
        for (int b = 0; b < NB; b++) {
            g_offE[b] = ds_pack(s);
            s = ds_add2(s, ds_of(g_blkE[b]));
        }
    }
    if (threadIdx.x == 32) {
        DS s = ds_make(0.f);
        for (int b = 0; b < NB; b++) {
            g_offW[b] = ds_pack(s);
            s = ds_add2(s, ds_of(g_blkW[b]));
        }
    }
}

// ---------------- P5: logp -> m,c ; prefW ; Tcut -----------------------------
__global__ __launch_bounds__(NT)
void p5_kernel() {
    __shared__ DS sh[NT];
    __shared__ int shMax;
    const int tid = threadIdx.x;
    const int t   = blockIdx.x * NT + tid;
    if (tid == 0) shMax = -1;

    // logp via scan of e
    float e = g_e[t];
    DS ve = (t < T_MAX) ? ds_make(e) : ds_make(0.f);
    DS exclE = block_scan_excl(ve, sh, tid, nullptr);
    DS logp = ds_add2(ds_add2(ds_make(INIT_LOGP_F), ds_of(g_offE[blockIdx.x])), exclE);

    int locMax = -1;
    if (t < T_MAX) {
        float p = expf(logp.hi);
        float m = p / (1.0f - p) - EPS_F;
        g_m[t] = m;
        g_c[t] = (m > 0.f) ? expf(-L1MIN_MAG * m) : 2.0f;
        if (m > 0.f) locMax = t;
    }
    atomicMax(&shMax, locMax);

    // prefW via scan of w
    float w = g_w[t];
    DS vw = (t < T_MAX) ? ds_make(w) : ds_make(0.f);
    DS exclW = block_scan_excl(vw, sh, tid, nullptr);
    DS pref = ds_add2(ds_of(g_offW[blockIdx.x]), exclW);
    if (t < T_MAX) {
        g_prefW[t] = pref.hi;
        if (t == T_MAX - 1) g_prefW[T_MAX] = ds_add(pref, w).hi;
    }

    __syncthreads();
    if (tid == 0 && shMax >= 0) atomicMax(&g_TcutM1, shMax);
}

// ---------------- scan: find first trigger per batch element -----------------
__global__ __launch_bounds__(256)
void scan_kernel(const float* __restrict__ u1, const float* __restrict__ u2) {
    const int t0 = blockIdx.y * CHUNK;
    const int Tc = g_TcutM1 + 1;
    if (t0 >= Tc) return;

    __shared__ float sm[CHUNK];
    __shared__ float sc[CHUNK];
    const int tid = threadIdx.x;
    if (tid < CHUNK) {
        int tt = t0 + tid;
        sm[tid] = (tt < T_MAX) ? g_m[tt] : -1.0f;
        sc[tid] = (tt < T_MAX) ? g_c[tt] : 2.0f;
    }
    __syncthreads();

    const int b = blockIdx.x * blockDim.x + tid;
    if (g_td[b] <= t0) return;   // already dead earlier (best-effort)

    const int n = min(CHUNK, Tc - t0);
    const float* p1 = u1 + (size_t)t0 * BATCH + b;
    const float* p2 = u2 + (size_t)t0 * BATCH + b;

    int i = 0;
    for (; i + 4 <= n; i += 4) {
        float c0 = p2[0], c1 = p2[BATCH], c2 = p2[2 * BATCH], c3 = p2[3 * BATCH];
        p2 += 4 * BATCH;
        // conservative necessary-condition filter: u2+eps must exceed exp(-27.632*m)
        bool f0 = (c0 + EPS_F) > sc[i + 0];
        bool f1 = (c1 + EPS_F) > sc[i + 1];
        bool f2 = (c2 + EPS_F) > sc[i + 2];
        bool f3 = (c3 + EPS_F) > sc[i + 3];
        if (f0 | f1 | f2 | f3) {
            float cv[4] = {c0, c1, c2, c3};
            bool  fv[4] = {f0, f1, f2, f3};
            #pragma unroll
            for (int j = 0; j < 4; j++) {
                if (fv[j]) {
                    float a  = p1[j * BATCH];
                    float l1 = __logf(a + EPS_F);
                    float l2 = __logf(cv[j] + EPS_F);
                    if (l2 > sm[i + j] * l1) {
                        atomicMin(&g_td[b], t0 + i + j);
                        return;
                    }
                }
            }
        }
        p1 += 4 * BATCH;
    }
    for (; i < n; ++i) {
        float c = p2[0];
        p2 += BATCH;
        if ((c + EPS_F) > sc[i]) {
            float l1 = __logf(p1[0] + EPS_F);
            float l2 = __logf(c + EPS_F);
            if (l2 > sm[i] * l1) {
                atomicMin(&g_td[b], t0 + i);
                return;
            }
        }
        p1 += BATCH;
    }
}

// ---------------- finalize: deterministic mean reduction ---------------------
__global__ __launch_bounds__(1024)
void finalize_kernel(float* __restrict__ out) {
    __shared__ double sh[1024];
    const int tid = threadIdx.x;
    double s = 0.0;
    for (int b = tid; b < BATCH; b += 1024)
        s += (double)g_prefW[g_td[b]];
    sh[tid] = s;
    __syncthreads();
    for (int ofs = 512; ofs > 0; ofs >>= 1) {
        if (tid < ofs) sh[tid] += sh[tid + ofs];
        __syncthreads();
    }
    if (tid == 0) out[0] = (float)(sh[0] * (1.0 / (double)BATCH));
}

// ---------------- launch -----------------------------------------------------
extern "C" void kernel_launch(void* const* d_in, const int* in_sizes, int n_in,
                              void* d_out, int out_size) {
    const float* acts = (const float*)d_in[0];
    const float* u1   = (const float*)d_in[1];
    const float* u2   = (const float*)d_in[2];
    float* out = (float*)d_out;

    p1_kernel<<<NB, NT>>>(acts);
    p2_kernel<<<1, 32>>>();
    p3_kernel<<<NB, NT>>>();
    p4_kernel<<<1, 64>>>();
    p5_kernel<<<NB, NT>>>();
    dim3 grid(BATCH / 256, NCHUNKS);
    scan_kernel<<<grid, 256>>>(u1, u2);
    finalize_kernel<<<1, 1024>>>(out);
}